// round 2
// baseline (speedup 1.0000x reference)
#include <cuda_runtime.h>

#define N_NODES 50000
#define N_EDGES 800000
#define HDIM    128
#define PAD     132                      // As row stride (floats), keeps 16B alignment, shifts banks
#define AS_FLOATS (64 * PAD)             // 8448
#define BS_FLOATS (HDIM * HDIM)          // 16384
#define SMEM_PROJ ((AS_FLOATS + BS_FLOATS) * 4)
#define SMEM_EDGE ((AS_FLOATS + BS_FLOATS) * 4)
#define SMEM_NODE ((2 * AS_FLOATS + BS_FLOATS) * 4)

// Scratch (device globals — no allocation allowed)
__device__ __align__(16) float g_P[N_NODES * 256];     // [Pa(+b1) | Pb] per node
__device__ __align__(16) float g_Hagg[N_NODES * HDIM]; // segment_sum of relu'd hidden
__device__ __align__(16) float g_deg[N_NODES];         // in-degree (float)
__device__ int g_idx_is64;                             // edge_index dtype flag

// ---------------------------------------------------------------------------
__device__ __forceinline__ void red4(float* p, float a, float b, float c, float d) {
    asm volatile("red.global.add.v4.f32 [%0], {%1,%2,%3,%4};"
                 :: "l"(p), "f"(a), "f"(b), "f"(c), "f"(d) : "memory");
}
__device__ __forceinline__ void red1(float* p, float v) {
    asm volatile("red.global.add.f32 [%0], %1;" :: "l"(p), "f"(v) : "memory");
}

// Load 64xK=128 row-major tile into As[64][PAD]; OOB rows zero-filled.
__device__ __forceinline__ void load_A(float* As, const float* __restrict__ src,
                                       int nrows, int tid) {
#pragma unroll
    for (int t = 0; t < 8; ++t) {
        int g  = tid + t * 256;          // 0..2047 float4 slots
        int r  = g >> 5;                 // 32 float4 per row
        int c4 = g & 31;
        float4 v = make_float4(0.f, 0.f, 0.f, 0.f);
        if (r < nrows) v = *(const float4*)(src + r * HDIM + c4 * 4);
        *(float4*)(As + r * PAD + c4 * 4) = v;
    }
}

// Load 128x128 row-major weight block into Bs.
__device__ __forceinline__ void load_B(float* Bs, const float* __restrict__ B, int tid) {
    const float4* s = (const float4*)B;
    float4* d = (float4*)Bs;
#pragma unroll
    for (int t = 0; t < 16; ++t) d[tid + t * 256] = s[tid + t * 256];
}

// C[64][128] (+)= As[64][128] @ Bs[128][128]; thread (tx,ty) owns rows ty*4..+3, cols tx*8..+7
__device__ __forceinline__ void gemm_tile(const float* __restrict__ As,
                                          const float* __restrict__ Bs,
                                          float acc[4][8], int tx, int ty) {
    const int r0 = ty * 4, c0 = tx * 8;
#pragma unroll 2
    for (int kk = 0; kk < HDIM; kk += 4) {
        float a[4][4];
#pragma unroll
        for (int i = 0; i < 4; ++i)
            *(float4*)a[i] = *(const float4*)(As + (r0 + i) * PAD + kk);
#pragma unroll
        for (int u = 0; u < 4; ++u) {
            float b[8];
            *(float4*)&b[0] = *(const float4*)(Bs + (kk + u) * HDIM + c0);
            *(float4*)&b[4] = *(const float4*)(Bs + (kk + u) * HDIM + c0 + 4);
#pragma unroll
            for (int i = 0; i < 4; ++i)
#pragma unroll
                for (int j = 0; j < 8; ++j)
                    acc[i][j] = fmaf(a[i][u], b[j], acc[i][j]);
        }
    }
}

__device__ __forceinline__ void zero_acc(float acc[4][8]) {
#pragma unroll
    for (int i = 0; i < 4; ++i)
#pragma unroll
        for (int j = 0; j < 8; ++j) acc[i][j] = 0.f;
}

// ---------------------------------------------------------------------------
// Detect edge_index width. If the tensor is int32, reading it as int64 packs
// two random node ids per word; the high half is nonzero w.p. ~1-2e-5 per
// entry, so "all 64 first values in [0, N_NODES)" <=> genuinely int64.
__global__ void k_detect(const long long* __restrict__ ei) {
    if (threadIdx.x == 0 && blockIdx.x == 0) {
        int ok = 1;
        for (int i = 0; i < 64; ++i) {
            long long v = ei[i];
            if (v < 0 || v >= N_NODES) { ok = 0; break; }
        }
        g_idx_is64 = ok;
    }
}

__global__ void k_zero() {
    int idx = blockIdx.x * blockDim.x + threadIdx.x;
    float4* p = (float4*)g_Hagg;
    const int n4 = N_NODES * HDIM / 4;
    for (int i = idx; i < n4; i += 256 * 256) p[i] = make_float4(0.f, 0.f, 0.f, 0.f);
    for (int i = idx; i < N_NODES; i += 256 * 256) g_deg[i] = 0.f;
}

// P = [x@W1a + b1 | x@W1b]
__global__ __launch_bounds__(256) void k_node_proj(const float* __restrict__ x,
                                                   const float* __restrict__ We1,
                                                   const float* __restrict__ be1) {
    extern __shared__ float smem[];
    float* As = smem;
    float* Bs = smem + AS_FLOATS;
    const int tid = threadIdx.x, tx = tid & 15, ty = tid >> 4;
    const int c0 = tx * 8, r0 = ty * 4;
    const int n0 = blockIdx.x * 64;
    const int nrows = min(64, N_NODES - n0);

    load_A(As, x + (size_t)n0 * HDIM, nrows, tid);
    load_B(Bs, We1, tid);                       // W1a = rows 0..127
    __syncthreads();
    float acc[4][8]; zero_acc(acc);
    gemm_tile(As, Bs, acc, tx, ty);
    float4 b0 = *(const float4*)(be1 + c0);
    float4 b1 = *(const float4*)(be1 + c0 + 4);
#pragma unroll
    for (int i = 0; i < 4; ++i) {
        int r = r0 + i;
        if (r < nrows) {
            float* dst = g_P + (size_t)(n0 + r) * 256 + c0;
            *(float4*)dst       = make_float4(acc[i][0]+b0.x, acc[i][1]+b0.y, acc[i][2]+b0.z, acc[i][3]+b0.w);
            *(float4*)(dst + 4) = make_float4(acc[i][4]+b1.x, acc[i][5]+b1.y, acc[i][6]+b1.z, acc[i][7]+b1.w);
        }
    }
    __syncthreads();
    load_B(Bs, We1 + 128 * HDIM, tid);          // W1b = rows 128..255
    __syncthreads();
    zero_acc(acc);
    gemm_tile(As, Bs, acc, tx, ty);
#pragma unroll
    for (int i = 0; i < 4; ++i) {
        int r = r0 + i;
        if (r < nrows) {
            float* dst = g_P + (size_t)(n0 + r) * 256 + 128 + c0;
            *(float4*)dst       = make_float4(acc[i][0], acc[i][1], acc[i][2], acc[i][3]);
            *(float4*)(dst + 4) = make_float4(acc[i][4], acc[i][5], acc[i][6], acc[i][7]);
        }
    }
}

// Persistent edge kernel: h = relu(ea@W1c + Pa[row] + Pb[col]); scatter h, deg
__global__ __launch_bounds__(256) void k_edge(const float* __restrict__ edge_attr,
                                              const void* __restrict__ edge_index,
                                              const float* __restrict__ We1) {
    extern __shared__ float smem[];
    float* As = smem;
    float* Bs = smem + AS_FLOATS;
    __shared__ int rows_s[64];
    __shared__ int cols_s[64];
    const int tid = threadIdx.x, tx = tid & 15, ty = tid >> 4;
    const int c0 = tx * 8;
    const int is64 = g_idx_is64;
    const long long* ei64 = (const long long*)edge_index;
    const int*       ei32 = (const int*)edge_index;
    load_B(Bs, We1 + 256 * HDIM, tid);          // W1c = rows 256..383

    const int ntiles = N_EDGES / 64;
    for (int t = blockIdx.x; t < ntiles; t += gridDim.x) {
        const long long e0 = (long long)t * 64;
        __syncthreads();                        // prior-tile consumers of As/idx done
        load_A(As, edge_attr + e0 * HDIM, 64, tid);
        if (tid < 64) {
            if (is64) {
                rows_s[tid] = (int)ei64[e0 + tid];
                cols_s[tid] = (int)ei64[N_EDGES + e0 + tid];
            } else {
                rows_s[tid] = ei32[e0 + tid];
                cols_s[tid] = ei32[N_EDGES + e0 + tid];
            }
        }
        __syncthreads();
        float acc[4][8]; zero_acc(acc);
        gemm_tile(As, Bs, acc, tx, ty);
#pragma unroll
        for (int i = 0; i < 4; ++i) {
            const int e = ty * 4 + i;
            const int r = rows_s[e], c = cols_s[e];
            const float* Pr = g_P + (size_t)r * 256 + c0;        // Pa (has b1)
            const float* Pc = g_P + (size_t)c * 256 + 128 + c0;  // Pb
            float4 pa0 = *(const float4*)Pr,       pa1 = *(const float4*)(Pr + 4);
            float4 pb0 = *(const float4*)Pc,       pb1 = *(const float4*)(Pc + 4);
            float h0 = fmaxf(acc[i][0] + pa0.x + pb0.x, 0.f);
            float h1 = fmaxf(acc[i][1] + pa0.y + pb0.y, 0.f);
            float h2 = fmaxf(acc[i][2] + pa0.z + pb0.z, 0.f);
            float h3 = fmaxf(acc[i][3] + pa0.w + pb0.w, 0.f);
            float h4 = fmaxf(acc[i][4] + pa1.x + pb1.x, 0.f);
            float h5 = fmaxf(acc[i][5] + pa1.y + pb1.y, 0.f);
            float h6 = fmaxf(acc[i][6] + pa1.z + pb1.z, 0.f);
            float h7 = fmaxf(acc[i][7] + pa1.w + pb1.w, 0.f);
            float* dst = g_Hagg + (size_t)c * HDIM + c0;
            red4(dst, h0, h1, h2, h3);
            red4(dst + 4, h4, h5, h6, h7);
        }
        if (tx == 0) {
#pragma unroll
            for (int i = 0; i < 4; ++i) red1(g_deg + cols_s[ty * 4 + i], 1.0f);
        }
    }
}

// agg = Hagg@We2 + deg*b2 ; out = relu([x|agg]@Wn1 + bn1)@Wn2 + bn2
__global__ __launch_bounds__(256) void k_node(const float* __restrict__ x,
                                              const float* __restrict__ We2,
                                              const float* __restrict__ be2,
                                              const float* __restrict__ Wn1,
                                              const float* __restrict__ bn1,
                                              const float* __restrict__ Wn2,
                                              const float* __restrict__ bn2,
                                              float* __restrict__ out) {
    extern __shared__ float smem[];
    float* As  = smem;
    float* As2 = smem + AS_FLOATS;
    float* Bs  = smem + 2 * AS_FLOATS;
    __shared__ float degs[64];
    const int tid = threadIdx.x, tx = tid & 15, ty = tid >> 4;
    const int c0 = tx * 8, r0 = ty * 4;
    const int n0 = blockIdx.x * 64;
    const int nrows = min(64, N_NODES - n0);

    // Stage A: agg tile = Hagg@We2 + deg*b2 -> As2 (row-major)
    load_A(As, g_Hagg + (size_t)n0 * HDIM, nrows, tid);
    load_B(Bs, We2, tid);
    if (tid < 64) degs[tid] = (n0 + tid < N_NODES) ? g_deg[n0 + tid] : 0.f;
    __syncthreads();
    float acc[4][8]; zero_acc(acc);
    gemm_tile(As, Bs, acc, tx, ty);
    {
        float4 b0 = *(const float4*)(be2 + c0);
        float4 b1 = *(const float4*)(be2 + c0 + 4);
#pragma unroll
        for (int i = 0; i < 4; ++i) {
            float d = degs[r0 + i];
            float* dst = As2 + (r0 + i) * PAD + c0;
            *(float4*)dst       = make_float4(acc[i][0]+d*b0.x, acc[i][1]+d*b0.y, acc[i][2]+d*b0.z, acc[i][3]+d*b0.w);
            *(float4*)(dst + 4) = make_float4(acc[i][4]+d*b1.x, acc[i][5]+d*b1.y, acc[i][6]+d*b1.z, acc[i][7]+d*b1.w);
        }
    }
    // Stage B: h = relu(x@Wn1x + agg@Wn1a + bn1) -> As
    __syncthreads();
    load_A(As, x + (size_t)n0 * HDIM, nrows, tid);
    load_B(Bs, Wn1, tid);                       // Wn1x = rows 0..127
    __syncthreads();
    zero_acc(acc);
    gemm_tile(As, Bs, acc, tx, ty);
    __syncthreads();
    load_B(Bs, Wn1 + 128 * HDIM, tid);          // Wn1a = rows 128..255
    __syncthreads();
    gemm_tile(As2, Bs, acc, tx, ty);            // accumulate
    {
        float4 b0 = *(const float4*)(bn1 + c0);
        float4 b1 = *(const float4*)(bn1 + c0 + 4);
#pragma unroll
        for (int i = 0; i < 4; ++i) {
            float* dst = As + (r0 + i) * PAD + c0;
            *(float4*)dst       = make_float4(fmaxf(acc[i][0]+b0.x,0.f), fmaxf(acc[i][1]+b0.y,0.f),
                                              fmaxf(acc[i][2]+b0.z,0.f), fmaxf(acc[i][3]+b0.w,0.f));
            *(float4*)(dst + 4) = make_float4(fmaxf(acc[i][4]+b1.x,0.f), fmaxf(acc[i][5]+b1.y,0.f),
                                              fmaxf(acc[i][6]+b1.z,0.f), fmaxf(acc[i][7]+b1.w,0.f));
        }
    }
    // Stage C: out = h@Wn2 + bn2
    __syncthreads();
    load_B(Bs, Wn2, tid);
    __syncthreads();
    zero_acc(acc);
    gemm_tile(As, Bs, acc, tx, ty);
    {
        float4 b0 = *(const float4*)(bn2 + c0);
        float4 b1 = *(const float4*)(bn2 + c0 + 4);
#pragma unroll
        for (int i = 0; i < 4; ++i) {
            int r = r0 + i;
            if (r < nrows) {
                float* dst = out + (size_t)(n0 + r) * HDIM + c0;
                *(float4*)dst       = make_float4(acc[i][0]+b0.x, acc[i][1]+b0.y, acc[i][2]+b0.z, acc[i][3]+b0.w);
                *(float4*)(dst + 4) = make_float4(acc[i][4]+b1.x, acc[i][5]+b1.y, acc[i][6]+b1.z, acc[i][7]+b1.w);
            }
        }
    }
}

// ---------------------------------------------------------------------------
extern "C" void kernel_launch(void* const* d_in, const int* in_sizes, int n_in,
                              void* d_out, int out_size) {
    const float* x          = (const float*)d_in[0];
    const void*  edge_index = d_in[1];
    const float* edge_attr  = (const float*)d_in[2];
    const float* We1        = (const float*)d_in[3];
    const float* be1        = (const float*)d_in[4];
    const float* We2        = (const float*)d_in[5];
    const float* be2        = (const float*)d_in[6];
    const float* Wn1        = (const float*)d_in[7];
    const float* bn1        = (const float*)d_in[8];
    const float* Wn2        = (const float*)d_in[9];
    const float* bn2        = (const float*)d_in[10];
    float* out = (float*)d_out;

    cudaFuncSetAttribute(k_node_proj, cudaFuncAttributeMaxDynamicSharedMemorySize, SMEM_PROJ);
    cudaFuncSetAttribute(k_edge,      cudaFuncAttributeMaxDynamicSharedMemorySize, SMEM_EDGE);
    cudaFuncSetAttribute(k_node,      cudaFuncAttributeMaxDynamicSharedMemorySize, SMEM_NODE);

    const int NB_NODE = (N_NODES + 63) / 64;    // 782
    k_detect<<<1, 32>>>((const long long*)edge_index);
    k_zero<<<256, 256>>>();
    k_node_proj<<<NB_NODE, 256, SMEM_PROJ>>>(x, We1, be1);
    k_edge<<<296, 256, SMEM_EDGE>>>(edge_attr, edge_index, We1);
    k_node<<<NB_NODE, 256, SMEM_NODE>>>(x, We2, be2, Wn1, bn1, Wn2, bn2, out);
}